// round 9
// baseline (speedup 1.0000x reference)
#include <cuda_runtime.h>
#include <math.h>

// Shapes:
//   x      [32,64,64,512] f32 NHWC
//   base_w [3,3,512,256]  HWIO
//   base_b [256]
//   cls_w  [1,1,256,9], cls_b [9]
//   reg_w  [1,1,256,36], reg_b [36]
//   out    [32,64,64,45]

#define NPIX (32 * 64 * 64)

__device__ float g_feat[(size_t)NPIX * 256];

// ---- packed f32x2 helpers (Blackwell FFMA2 path; ptxas won't auto-fuse) ----
__device__ __forceinline__ void fma2(unsigned long long& d,
                                     unsigned long long a,
                                     unsigned long long b)
{
    asm("fma.rn.f32x2 %0, %1, %2, %0;" : "+l"(d) : "l"(a), "l"(b));
}
__device__ __forceinline__ unsigned long long dup2(float v)
{
    unsigned long long r;
    unsigned u = __float_as_uint(v);
    asm("mov.b64 %0, {%1, %1};" : "=l"(r) : "r"(u));
    return r;
}

// ---------------------------------------------------------------------------
// Stage 1: 3x3 conv + bias + ReLU, implicit GEMM.
//   M = NPIX, N = 256, K = 9*512. BM=128, BN=128, BK=8, 256 thr, 8x8/thread.
//   Double-buffered SMEM (1 bar/k-tile) + packed FFMA2 inner product.
// ---------------------------------------------------------------------------
__global__ void __launch_bounds__(256, 2)
conv3x3_relu_kernel(const float* __restrict__ x,
                    const float* __restrict__ wbase,
                    const float* __restrict__ bbase)
{
    __shared__ float As[2][8][132];   // transposed [k][m], pad 132 (conflict-free)
    __shared__ float Bs[2][8][128];

    const int tid  = threadIdx.x;
    const int nblk = blockIdx.x;      // 0..1
    const int mblk = blockIdx.y;      // 0..1023

    // global-load mapping
    const int arow = tid >> 1;        // 0..127 pixel
    const int acol = tid & 1;         // k-quad
    const int brow = tid >> 5;        // 0..7 k row
    const int bcol = tid & 31;        // n-quad

    const int p  = mblk * 128 + arow;
    const int pb = p >> 12;
    const int ph = (p >> 6) & 63;
    const int pw = p & 63;

    // compute mapping: 16x16 threads, 8x8 outputs
    const int tr = tid >> 4;
    const int tc = tid & 15;
    const int m0 = tr * 8;
    const int n0 = tc * 8;

    // packed accumulators: acc2[i][j2] = {acc[i][2j2], acc[i][2j2+1]}
    unsigned long long acc2[8][4];
#pragma unroll
    for (int i = 0; i < 8; i++)
#pragma unroll
        for (int j = 0; j < 4; j++) acc2[i][j] = 0ull;

    int buf = 0;

#pragma unroll 1
    for (int pos = 0; pos < 9; pos++) {
        const int ky  = pos / 3;
        const int kx  = pos - ky * 3;
        const int hin = ph + ky - 1;
        const int win = pw + kx - 1;
        const bool valid = ((unsigned)hin < 64u) && ((unsigned)win < 64u);
        const float* aptr = x + ((((pb * 64 + hin) * 64) + win) * 512 + acol * 4);
        const float* bptr = wbase + (pos * 512 * 256 + brow * 256 + nblk * 128 + bcol * 4);

        // prologue: stage cc=0 into the idle buffer
        {
            float4 av = make_float4(0.f, 0.f, 0.f, 0.f);
            if (valid) av = *(const float4*)(aptr);
            const float4 bv = *(const float4*)(bptr);
            const int nb = buf ^ 1;
            As[nb][acol * 4 + 0][arow] = av.x;
            As[nb][acol * 4 + 1][arow] = av.y;
            As[nb][acol * 4 + 2][arow] = av.z;
            As[nb][acol * 4 + 3][arow] = av.w;
            *(float4*)(&Bs[nb][brow][bcol * 4]) = bv;
            __syncthreads();
            buf = nb;
        }

#pragma unroll 1
        for (int cc = 0; cc < 64; cc++) {
            float4 av2, bv2;
            if (cc < 63) {
                av2 = make_float4(0.f, 0.f, 0.f, 0.f);
                if (valid) av2 = *(const float4*)(aptr + (cc + 1) * 8);
                bv2 = *(const float4*)(bptr + (cc + 1) * 2048);
            }

#pragma unroll
            for (int k = 0; k < 8; k++) {
                const float* asrc = &As[buf][k][m0];
                const float4 a0 = *(const float4*)(asrc);
                const float4 a1 = *(const float4*)(asrc + 4);
                const unsigned long long* bp =
                    (const unsigned long long*)(&Bs[buf][k][n0]);
                const unsigned long long b0 = bp[0], b1 = bp[1],
                                         b2 = bp[2], b3 = bp[3];

                unsigned long long ad;
                ad = dup2(a0.x);
                fma2(acc2[0][0], ad, b0); fma2(acc2[0][1], ad, b1);
                fma2(acc2[0][2], ad, b2); fma2(acc2[0][3], ad, b3);
                ad = dup2(a0.y);
                fma2(acc2[1][0], ad, b0); fma2(acc2[1][1], ad, b1);
                fma2(acc2[1][2], ad, b2); fma2(acc2[1][3], ad, b3);
                ad = dup2(a0.z);
                fma2(acc2[2][0], ad, b0); fma2(acc2[2][1], ad, b1);
                fma2(acc2[2][2], ad, b2); fma2(acc2[2][3], ad, b3);
                ad = dup2(a0.w);
                fma2(acc2[3][0], ad, b0); fma2(acc2[3][1], ad, b1);
                fma2(acc2[3][2], ad, b2); fma2(acc2[3][3], ad, b3);
                ad = dup2(a1.x);
                fma2(acc2[4][0], ad, b0); fma2(acc2[4][1], ad, b1);
                fma2(acc2[4][2], ad, b2); fma2(acc2[4][3], ad, b3);
                ad = dup2(a1.y);
                fma2(acc2[5][0], ad, b0); fma2(acc2[5][1], ad, b1);
                fma2(acc2[5][2], ad, b2); fma2(acc2[5][3], ad, b3);
                ad = dup2(a1.z);
                fma2(acc2[6][0], ad, b0); fma2(acc2[6][1], ad, b1);
                fma2(acc2[6][2], ad, b2); fma2(acc2[6][3], ad, b3);
                ad = dup2(a1.w);
                fma2(acc2[7][0], ad, b0); fma2(acc2[7][1], ad, b1);
                fma2(acc2[7][2], ad, b2); fma2(acc2[7][3], ad, b3);
            }

            if (cc < 63) {
                const int nb = buf ^ 1;
                As[nb][acol * 4 + 0][arow] = av2.x;
                As[nb][acol * 4 + 1][arow] = av2.y;
                As[nb][acol * 4 + 2][arow] = av2.z;
                As[nb][acol * 4 + 3][arow] = av2.w;
                *(float4*)(&Bs[nb][brow][bcol * 4]) = bv2;
                __syncthreads();
                buf = nb;
            }
        }
    }

    // epilogue: bias + ReLU, store feat tile
    float bias[8];
#pragma unroll
    for (int j = 0; j < 8; j++) bias[j] = bbase[nblk * 128 + n0 + j];

#pragma unroll
    for (int i = 0; i < 8; i++) {
        const int pm = mblk * 128 + m0 + i;
        float* dst = g_feat + (size_t)pm * 256 + nblk * 128 + n0;
        float v[8];
#pragma unroll
        for (int j2 = 0; j2 < 4; j2++) {
            v[2 * j2 + 0] = __uint_as_float((unsigned)(acc2[i][j2] & 0xffffffffull));
            v[2 * j2 + 1] = __uint_as_float((unsigned)(acc2[i][j2] >> 32));
        }
        float4 v0, v1;
        v0.x = fmaxf(v[0] + bias[0], 0.f);
        v0.y = fmaxf(v[1] + bias[1], 0.f);
        v0.z = fmaxf(v[2] + bias[2], 0.f);
        v0.w = fmaxf(v[3] + bias[3], 0.f);
        v1.x = fmaxf(v[4] + bias[4], 0.f);
        v1.y = fmaxf(v[5] + bias[5], 0.f);
        v1.z = fmaxf(v[6] + bias[6], 0.f);
        v1.w = fmaxf(v[7] + bias[7], 0.f);
        *(float4*)(dst)     = v0;
        *(float4*)(dst + 4) = v1;
    }
}

// ---------------------------------------------------------------------------
// Stage 2: fused 1x1 heads + sigmoid + anchor filter + concat store.
// ---------------------------------------------------------------------------
__global__ void __launch_bounds__(256)
rpn_head_kernel(const float* __restrict__ cls_w,
                const float* __restrict__ cls_b,
                const float* __restrict__ reg_w,
                const float* __restrict__ reg_b,
                float* __restrict__ out)
{
    __shared__ float wsm[256 * 45];
    for (int idx = threadIdx.x; idx < 256 * 45; idx += 256) {
        const int c = idx / 45;
        const int j = idx - c * 45;
        wsm[idx] = (j < 36) ? reg_w[c * 36 + j] : cls_w[c * 9 + (j - 36)];
    }
    __syncthreads();

    const int p = blockIdx.x * 256 + threadIdx.x;
    const float* f = g_feat + (size_t)p * 256;

    float acc[45];
#pragma unroll
    for (int j = 0; j < 45; j++) acc[j] = 0.0f;

#pragma unroll 1
    for (int c4 = 0; c4 < 64; c4++) {
        const float4 fv = *(const float4*)(f + c4 * 4);
        const float* w0 = &wsm[(c4 * 4 + 0) * 45];
        const float* w1 = &wsm[(c4 * 4 + 1) * 45];
        const float* w2 = &wsm[(c4 * 4 + 2) * 45];
        const float* w3 = &wsm[(c4 * 4 + 3) * 45];
#pragma unroll
        for (int j = 0; j < 45; j++) {
            float t = acc[j];
            t = fmaf(fv.x, w0[j], t);
            t = fmaf(fv.y, w1[j], t);
            t = fmaf(fv.z, w2[j], t);
            t = fmaf(fv.w, w3[j], t);
            acc[j] = t;
        }
    }

#pragma unroll
    for (int j = 0; j < 36; j++) acc[j] += reg_b[j];
#pragma unroll
    for (int a = 0; a < 9; a++) {
        const float z = acc[36 + a] + cls_b[a];
        acc[36 + a] = 1.0f / (1.0f + expf(-z));
    }

    float* o = out + (size_t)p * 45;
#pragma unroll
    for (int a = 0; a < 9; a++) {
        const bool keep = (acc[36 + a] > 0.7f) &&
                          (acc[4 * a + 2] > 10.0f) &&
                          (acc[4 * a + 3] > 10.0f);
        const float m = keep ? 1.0f : 0.0f;
        o[4 * a + 0] = acc[4 * a + 0] * m;
        o[4 * a + 1] = acc[4 * a + 1] * m;
        o[4 * a + 2] = acc[4 * a + 2] * m;
        o[4 * a + 3] = acc[4 * a + 3] * m;
        o[36 + a]    = acc[36 + a];
    }
}

extern "C" void kernel_launch(void* const* d_in, const int* in_sizes, int n_in,
                              void* d_out, int out_size)
{
    const float* x      = (const float*)d_in[0];
    const float* base_w = (const float*)d_in[1];
    const float* base_b = (const float*)d_in[2];
    const float* cls_w  = (const float*)d_in[3];
    const float* cls_b  = (const float*)d_in[4];
    const float* reg_w  = (const float*)d_in[5];
    const float* reg_b  = (const float*)d_in[6];
    float* out = (float*)d_out;

    dim3 g1(2, 1024, 1);
    conv3x3_relu_kernel<<<g1, 256>>>(x, base_w, base_b);
    rpn_head_kernel<<<512, 256>>>(cls_w, cls_b, reg_w, reg_b, out);
}

// round 13
// speedup vs baseline: 1.3191x; 1.3191x over previous
#include <cuda_runtime.h>
#include <math.h>
#include <stdint.h>

// Shapes:
//   x      [32,64,64,512] f32 NHWC
//   base_w [3,3,512,256]  HWIO   (flattened: w[kk*256+n], kk = pos*512+c)
//   base_b [256]
//   cls_w  [1,1,256,9], cls_b [9]
//   reg_w  [1,1,256,36], reg_b [36]
//   out    [32,64,64,45]

#define NPIX    (32 * 64 * 64)
#define KTOT    4608
#define NSTEPS  288                     // KTOT / 16
#define A_STRIDE 20                     // floats per A smem row (16 + 4 pad)
#define B_STRIDE 136                    // floats per B smem row (128 + 8 pad)
#define A_HL    (128 * A_STRIDE * 4)    // 10240 B per A half (hi or lo)
#define B_HL    (16 * B_STRIDE * 4)     // 8704 B per B half
#define ABYTES  (2 * A_HL)              // 20480
#define BBYTES  (2 * B_HL)              // 17408
#define STAGE   (ABYTES + BBYTES)       // 37888
#define SMEM_TOTAL (2 * STAGE)          // 75776

#define DELTA_REG 2e-3f
#define DELTA_OBJ 3e-5f

__device__ float g_feat[(size_t)NPIX * 256];
__device__ __align__(256) float g_xhi[(size_t)NPIX * 512];
__device__ __align__(256) float g_xlo[(size_t)NPIX * 512];
__device__ __align__(256) float g_Bhi[(size_t)KTOT * 256];
__device__ __align__(256) float g_Blo[(size_t)KTOT * 256];
__device__ __align__(256) float g_zero[16];   // stays zero (never written)
__device__ int g_count;
__device__ int g_list[NPIX];

// ---------------- helpers ----------------
__device__ __forceinline__ float tf32r(float x) {
    float r;
    asm("cvt.rna.tf32.f32 %0, %1;" : "=f"(r) : "f"(x));
    return r;
}
__device__ __forceinline__ uint32_t smem_u32(const void* p) {
    uint32_t a;
    asm("{ .reg .u64 t; cvta.to.shared.u64 t, %1; cvt.u32.u64 %0, t; }"
        : "=r"(a) : "l"(p));
    return a;
}
__device__ __forceinline__ void cp16(uint32_t d, const void* s) {
    asm volatile("cp.async.ca.shared.global [%0], [%1], 16;"
                 :: "r"(d), "l"(s) : "memory");
}
__device__ __forceinline__ uint32_t lds32b(uint32_t a) {
    uint32_t v;
    asm("ld.shared.b32 %0, [%1];" : "=r"(v) : "r"(a));
    return v;
}
__device__ __forceinline__ void mma_tf32(float* c, const uint32_t* a,
                                         const uint32_t* b) {
    asm volatile(
        "mma.sync.aligned.m16n8k8.row.col.f32.tf32.tf32.f32 "
        "{%0,%1,%2,%3}, {%4,%5,%6,%7}, {%8,%9}, {%0,%1,%2,%3};"
        : "+f"(c[0]), "+f"(c[1]), "+f"(c[2]), "+f"(c[3])
        : "r"(a[0]), "r"(a[1]), "r"(a[2]), "r"(a[3]), "r"(b[0]), "r"(b[1]));
}

// ---------------------------------------------------------------------------
// Reset: zero the repair counter (every replay).
// ---------------------------------------------------------------------------
__global__ void reset_kernel() { g_count = 0; }

// ---------------------------------------------------------------------------
// Prep: elementwise tf32 hi/lo split of x and base_w.
// ---------------------------------------------------------------------------
__global__ void prep_x_kernel(const float* __restrict__ x)
{
    const size_t i = ((size_t)blockIdx.x * 256 + threadIdx.x) * 4;
    const float4 v = *(const float4*)(x + i);
    float4 h, l;
    h.x = tf32r(v.x); l.x = tf32r(v.x - h.x);
    h.y = tf32r(v.y); l.y = tf32r(v.y - h.y);
    h.z = tf32r(v.z); l.z = tf32r(v.z - h.z);
    h.w = tf32r(v.w); l.w = tf32r(v.w - h.w);
    *(float4*)(g_xhi + i) = h;
    *(float4*)(g_xlo + i) = l;
}
__global__ void prep_b_kernel(const float* __restrict__ w)
{
    const size_t i = ((size_t)blockIdx.x * 256 + threadIdx.x) * 4;
    const float4 v = *(const float4*)(w + i);
    float4 h, l;
    h.x = tf32r(v.x); l.x = tf32r(v.x - h.x);
    h.y = tf32r(v.y); l.y = tf32r(v.y - h.y);
    h.z = tf32r(v.z); l.z = tf32r(v.z - h.z);
    h.w = tf32r(v.w); l.w = tf32r(v.w - h.w);
    *(float4*)(g_Bhi + i) = h;
    *(float4*)(g_Blo + i) = l;
}

// ---------------------------------------------------------------------------
// Stage 1: 3x3 conv + bias + ReLU via mma.sync TF32x3 implicit GEMM.
// CTA: M=128 pixels (2 image rows), N=128 channels, K=4608 in 288 steps of 16.
// 8 warps, warp tile 32x64. Double-buffered SMEM, cp.async prefetch.
// ---------------------------------------------------------------------------
__global__ void __launch_bounds__(256, 1)
conv_mma_kernel(const float* __restrict__ bbase)
{
    extern __shared__ char smem[];
    const uint32_t sb = smem_u32(smem);
    const int tid  = threadIdx.x;
    const int wid  = tid >> 5;
    const int lane = tid & 31;
    const int g    = lane >> 2;
    const int t    = lane & 3;
    const int nblk = blockIdx.x;         // 0..1
    const int mblk = blockIdx.y;         // 0..1023
    const int wm   = (wid >> 1) * 32;
    const int wn   = (wid & 1) * 64;

    const int arow  = tid >> 1;
    const int ahalf = tid & 1;
    const int p  = mblk * 128 + arow;
    const int pb = p >> 12;
    const int ph = (p >> 6) & 63;
    const int pw = p & 63;
    const int brow = tid >> 4;
    const int bc16 = tid & 15;

    float bias[16];
#pragma unroll
    for (int ni = 0; ni < 8; ni++) {
        const int ch = nblk * 128 + wn + ni * 8 + 2 * t;
        bias[2 * ni + 0] = __ldg(&bbase[ch + 0]);
        bias[2 * ni + 1] = __ldg(&bbase[ch + 1]);
    }

    float C[2][8][4];
#pragma unroll
    for (int mi = 0; mi < 2; mi++)
#pragma unroll
        for (int ni = 0; ni < 8; ni++)
#pragma unroll
            for (int r = 0; r < 4; r++) C[mi][ni][r] = 0.0f;

    auto fill = [&](int step, int stg) {
        const uint32_t base = sb + (uint32_t)stg * STAGE;
        const int pos = step >> 5;
        const int ky  = pos / 3;
        const int kx  = pos - ky * 3;
        const int hin = ph + ky - 1;
        const int win = pw + kx - 1;
        const bool valid = ((unsigned)hin < 64u) && ((unsigned)win < 64u);
        const int c0 = (step & 31) * 16;
        const float* xsrc = ahalf ? g_xlo : g_xhi;
        const char* asrc = valid
            ? (const char*)(xsrc + ((size_t)((pb * 64 + hin) * 64 + win)) * 512 + c0)
            : (const char*)g_zero;
        const uint32_t adst = base + (uint32_t)ahalf * A_HL +
                              (uint32_t)arow * (A_STRIDE * 4);
#pragma unroll
        for (int i = 0; i < 4; i++) cp16(adst + i * 16, asrc + i * 16);

#pragma unroll
        for (int h = 0; h < 2; h++) {
            const float* bs = (h ? g_Blo : g_Bhi) +
                              ((size_t)(step * 16 + brow)) * 256 + nblk * 128;
            const uint32_t bdst = base + ABYTES + (uint32_t)h * B_HL +
                                  (uint32_t)brow * (B_STRIDE * 4);
#pragma unroll
            for (int j = 0; j < 2; j++) {
                const int c16 = bc16 + j * 16;
                cp16(bdst + c16 * 16, (const char*)bs + c16 * 16);
            }
        }
        asm volatile("cp.async.commit_group;" ::: "memory");
    };

    fill(0, 0);

#pragma unroll 1
    for (int step = 0; step < NSTEPS; step++) {
        const int cur = step & 1;
        asm volatile("cp.async.wait_group 0;" ::: "memory");
        __syncthreads();
        if (step + 1 < NSTEPS) fill(step + 1, cur ^ 1);

        const uint32_t base    = sb + (uint32_t)cur * STAGE;
        const uint32_t bbase_s = base + ABYTES;

#pragma unroll
        for (int k8 = 0; k8 < 2; k8++) {
            const int k0 = k8 * 8;
            uint32_t ah[2][4], al[2][4];
#pragma unroll
            for (int mi = 0; mi < 2; mi++) {
                const uint32_t ad = base + (uint32_t)(wm + mi * 16 + g) * (A_STRIDE * 4)
                                         + (uint32_t)(k0 + t) * 4;
                ah[mi][0] = lds32b(ad);
                ah[mi][1] = lds32b(ad + 8 * A_STRIDE * 4);
                ah[mi][2] = lds32b(ad + 16);
                ah[mi][3] = lds32b(ad + 8 * A_STRIDE * 4 + 16);
                al[mi][0] = lds32b(ad + A_HL);
                al[mi][1] = lds32b(ad + A_HL + 8 * A_STRIDE * 4);
                al[mi][2] = lds32b(ad + A_HL + 16);
                al[mi][3] = lds32b(ad + A_HL + 8 * A_STRIDE * 4 + 16);
            }
            uint32_t bh[8][2], bl[8][2];
#pragma unroll
            for (int ni = 0; ni < 8; ni++) {
                const uint32_t bd = bbase_s + (uint32_t)(k0 + t) * (B_STRIDE * 4)
                                            + (uint32_t)(wn + ni * 8 + g) * 4;
                bh[ni][0] = lds32b(bd);
                bh[ni][1] = lds32b(bd + 4 * B_STRIDE * 4);
                bl[ni][0] = lds32b(bd + B_HL);
                bl[ni][1] = lds32b(bd + B_HL + 4 * B_STRIDE * 4);
            }
#pragma unroll
            for (int mi = 0; mi < 2; mi++)
#pragma unroll
                for (int ni = 0; ni < 8; ni++)
                    mma_tf32(C[mi][ni], ah[mi], bh[ni]);
#pragma unroll
            for (int mi = 0; mi < 2; mi++)
#pragma unroll
                for (int ni = 0; ni < 8; ni++)
                    mma_tf32(C[mi][ni], ah[mi], bl[ni]);
#pragma unroll
            for (int mi = 0; mi < 2; mi++)
#pragma unroll
                for (int ni = 0; ni < 8; ni++)
                    mma_tf32(C[mi][ni], al[mi], bh[ni]);
        }
    }

#pragma unroll
    for (int mi = 0; mi < 2; mi++) {
        const int row0 = mblk * 128 + wm + mi * 16 + g;
#pragma unroll
        for (int ni = 0; ni < 8; ni++) {
            const int ch = nblk * 128 + wn + ni * 8 + 2 * t;
            float2 v0, v1;
            v0.x = fmaxf(C[mi][ni][0] + bias[2 * ni + 0], 0.f);
            v0.y = fmaxf(C[mi][ni][1] + bias[2 * ni + 1], 0.f);
            v1.x = fmaxf(C[mi][ni][2] + bias[2 * ni + 0], 0.f);
            v1.y = fmaxf(C[mi][ni][3] + bias[2 * ni + 1], 0.f);
            *(float2*)(g_feat + (size_t)row0 * 256 + ch)       = v0;
            *(float2*)(g_feat + (size_t)(row0 + 8) * 256 + ch) = v1;
        }
    }
}

// ---------------------------------------------------------------------------
// Stage 2: fused 1x1 heads + sigmoid + anchor filter + concat store.
// Flags pixels with any anchor within delta of a decision threshold.
// ---------------------------------------------------------------------------
__global__ void __launch_bounds__(256)
rpn_head_kernel(const float* __restrict__ cls_w,
                const float* __restrict__ cls_b,
                const float* __restrict__ reg_w,
                const float* __restrict__ reg_b,
                float* __restrict__ out)
{
    __shared__ float wsm[256 * 45];
    for (int idx = threadIdx.x; idx < 256 * 45; idx += 256) {
        const int c = idx / 45;
        const int j = idx - c * 45;
        wsm[idx] = (j < 36) ? reg_w[c * 36 + j] : cls_w[c * 9 + (j - 36)];
    }
    __syncthreads();

    const int p = blockIdx.x * 256 + threadIdx.x;
    const float* f = g_feat + (size_t)p * 256;

    float acc[45];
#pragma unroll
    for (int j = 0; j < 45; j++) acc[j] = 0.0f;

#pragma unroll 1
    for (int c4 = 0; c4 < 64; c4++) {
        const float4 fv = *(const float4*)(f + c4 * 4);
        const float* w0 = &wsm[(c4 * 4 + 0) * 45];
        const float* w1 = &wsm[(c4 * 4 + 1) * 45];
        const float* w2 = &wsm[(c4 * 4 + 2) * 45];
        const float* w3 = &wsm[(c4 * 4 + 3) * 45];
#pragma unroll
        for (int j = 0; j < 45; j++) {
            float tt = acc[j];
            tt = fmaf(fv.x, w0[j], tt);
            tt = fmaf(fv.y, w1[j], tt);
            tt = fmaf(fv.z, w2[j], tt);
            tt = fmaf(fv.w, w3[j], tt);
            acc[j] = tt;
        }
    }

#pragma unroll
    for (int j = 0; j < 36; j++) acc[j] += reg_b[j];
#pragma unroll
    for (int a = 0; a < 9; a++) {
        const float z = acc[36 + a] + cls_b[a];
        acc[36 + a] = 1.0f / (1.0f + expf(-z));
    }

    bool flag = false;
    float* o = out + (size_t)p * 45;
#pragma unroll
    for (int a = 0; a < 9; a++) {
        const float obj = acc[36 + a];
        const float w2v = acc[4 * a + 2];
        const float h2v = acc[4 * a + 3];
        flag |= (fabsf(w2v - 10.0f) < DELTA_REG) ||
                (fabsf(h2v - 10.0f) < DELTA_REG) ||
                (fabsf(obj - 0.7f)  < DELTA_OBJ);
        const bool keep = (obj > 0.7f) && (w2v > 10.0f) && (h2v > 10.0f);
        const float m = keep ? 1.0f : 0.0f;
        o[4 * a + 0] = acc[4 * a + 0] * m;
        o[4 * a + 1] = acc[4 * a + 1] * m;
        o[4 * a + 2] = w2v * m;
        o[4 * a + 3] = h2v * m;
        o[36 + a]    = obj;
    }
    if (flag) {
        const int i = atomicAdd(&g_count, 1);
        g_list[i] = p;
    }
}

// ---------------------------------------------------------------------------
// Stage 3: exact fp32 repair of flagged (threshold-adjacent) pixels.
// One block per list entry (grid-stride). Recompute feat row + head exactly.
// ---------------------------------------------------------------------------
__global__ void __launch_bounds__(256)
repair_kernel(const float* __restrict__ x,  const float* __restrict__ w,
              const float* __restrict__ bbase,
              const float* __restrict__ cls_w, const float* __restrict__ cls_b,
              const float* __restrict__ reg_w, const float* __restrict__ reg_b,
              float* __restrict__ out)
{
    __shared__ float xs[KTOT];
    __shared__ float feats[256];
    __shared__ float hsm[45];
    const int tid = threadIdx.x;
    const int cnt = g_count;

    for (int it = blockIdx.x; it < cnt; it += gridDim.x) {
        const int p  = g_list[it];
        const int pb = p >> 12;
        const int ph = (p >> 6) & 63;
        const int pw = p & 63;

#pragma unroll 1
        for (int pos = 0; pos < 9; pos++) {
            const int ky = pos / 3;
            const int kx = pos - ky * 3;
            const int hin = ph + ky - 1;
            const int win = pw + kx - 1;
            const bool valid = ((unsigned)hin < 64u) && ((unsigned)win < 64u);
            const float* src = x + ((size_t)((pb * 64 + hin) * 64 + win)) * 512;
#pragma unroll
            for (int c = tid; c < 512; c += 256)
                xs[pos * 512 + c] = valid ? src[c] : 0.0f;
        }
        __syncthreads();

        float a0 = 0.f, a1 = 0.f, a2 = 0.f, a3 = 0.f;
#pragma unroll 4
        for (int kk = 0; kk < KTOT; kk += 4) {
            a0 = fmaf(xs[kk + 0], w[(size_t)(kk + 0) * 256 + tid], a0);
            a1 = fmaf(xs[kk + 1], w[(size_t)(kk + 1) * 256 + tid], a1);
            a2 = fmaf(xs[kk + 2], w[(size_t)(kk + 2) * 256 + tid], a2);
            a3 = fmaf(xs[kk + 3], w[(size_t)(kk + 3) * 256 + tid], a3);
        }
        feats[tid] = fmaxf((a0 + a1) + (a2 + a3) + bbase[tid], 0.0f);
        __syncthreads();

        if (tid < 45) {
            float a = 0.f;
            if (tid < 36) {
#pragma unroll 4
                for (int c = 0; c < 256; c++)
                    a = fmaf(feats[c], reg_w[c * 36 + tid], a);
                a += reg_b[tid];
            } else {
                const int j = tid - 36;
#pragma unroll 4
                for (int c = 0; c < 256; c++)
                    a = fmaf(feats[c], cls_w[c * 9 + j], a);
                a = 1.0f / (1.0f + expf(-(a + cls_b[j])));
            }
            hsm[tid] = a;
        }
        __syncthreads();

        if (tid < 9) {
            const int a4 = tid * 4;
            const float obj = hsm[36 + tid];
            const bool keep = (obj > 0.7f) && (hsm[a4 + 2] > 10.0f) &&
                              (hsm[a4 + 3] > 10.0f);
            const float m = keep ? 1.0f : 0.0f;
            float* o = out + (size_t)p * 45;
            o[a4 + 0] = hsm[a4 + 0] * m;
            o[a4 + 1] = hsm[a4 + 1] * m;
            o[a4 + 2] = hsm[a4 + 2] * m;
            o[a4 + 3] = hsm[a4 + 3] * m;
            o[36 + tid] = obj;
        }
        __syncthreads();
    }
}

extern "C" void kernel_launch(void* const* d_in, const int* in_sizes, int n_in,
                              void* d_out, int out_size)
{
    const float* x      = (const float*)d_in[0];
    const float* base_w = (const float*)d_in[1];
    const float* base_b = (const float*)d_in[2];
    const float* cls_w  = (const float*)d_in[3];
    const float* cls_b  = (const float*)d_in[4];
    const float* reg_w  = (const float*)d_in[5];
    const float* reg_b  = (const float*)d_in[6];
    float* out = (float*)d_out;

    cudaFuncSetAttribute(conv_mma_kernel,
                         cudaFuncAttributeMaxDynamicSharedMemorySize, SMEM_TOTAL);

    reset_kernel<<<1, 1>>>();
    prep_x_kernel<<<(NPIX * 512 / 4) / 256, 256>>>(x);
    prep_b_kernel<<<(KTOT * 256 / 4) / 256, 256>>>(base_w);

    dim3 g1(2, 1024, 1);
    conv_mma_kernel<<<g1, 256, SMEM_TOTAL>>>(base_b);
    rpn_head_kernel<<<512, 256>>>(cls_w, cls_b, reg_w, reg_b, out);
    repair_kernel<<<256, 256>>>(x, base_w, base_b, cls_w, cls_b,
                                reg_w, reg_b, out);
}

// round 14
// speedup vs baseline: 1.6405x; 1.2437x over previous
#include <cuda_runtime.h>
#include <cuda_bf16.h>
#include <math.h>
#include <stdint.h>

// Shapes:
//   x      [32,64,64,512] f32 NHWC
//   base_w [3,3,512,256]  HWIO   (flattened: w[kk*256+n], kk = pos*512+c)
//   base_b [256]
//   cls_w  [1,1,256,9], cls_b [9]
//   reg_w  [1,1,256,36], reg_b [36]
//   out    [32,64,64,45]

#define NPIX    (32 * 64 * 64)
#define KTOT    4608
#define KCH     144                 // k chunks of 32
#define NSTEPS  144
#define AROW_B  80                  // 32 bf16 = 64B + 16B pad (conflict-free)
#define A_HL    (128 * AROW_B)      // 10240 B per A half
#define B_HL    (128 * AROW_B)      // 10240 B per B half (128 n-rows)
#define ABYTES  (2 * A_HL)          // 20480
#define BBYTES  (2 * B_HL)          // 20480
#define STAGE   (ABYTES + BBYTES)   // 40960
#define NSTAGE  3
#define SMEM_TOTAL (NSTAGE * STAGE) // 122880

#define DELTA_REG 5e-3f
#define DELTA_OBJ 5e-4f

__device__ float g_feat[(size_t)NPIX * 256];
__device__ __align__(256) __nv_bfloat16 g_xh16[(size_t)NPIX * 512];
__device__ __align__(256) __nv_bfloat16 g_xl16[(size_t)NPIX * 512];
// B chunks: [kc][n 256][k 32] bf16, so the conv-side fill is a linear copy.
__device__ __align__(256) __nv_bfloat16 g_Bh16[(size_t)KCH * 256 * 32];
__device__ __align__(256) __nv_bfloat16 g_Bl16[(size_t)KCH * 256 * 32];
__device__ __align__(256) float g_zero[16];   // 64B, stays zero
__device__ int g_count;
__device__ int g_list[NPIX];

// ---------------- helpers ----------------
__device__ __forceinline__ uint32_t smem_u32(const void* p) {
    uint32_t a;
    asm("{ .reg .u64 t; cvta.to.shared.u64 t, %1; cvt.u32.u64 %0, t; }"
        : "=r"(a) : "l"(p));
    return a;
}
__device__ __forceinline__ void cp16(uint32_t d, const void* s) {
    asm volatile("cp.async.ca.shared.global [%0], [%1], 16;"
                 :: "r"(d), "l"(s) : "memory");
}
__device__ __forceinline__ uint32_t lds32b(uint32_t a) {
    uint32_t v;
    asm("ld.shared.b32 %0, [%1];" : "=r"(v) : "r"(a));
    return v;
}
__device__ __forceinline__ void mma_bf16(float* c, const uint32_t* a,
                                         const uint32_t* b) {
    asm volatile(
        "mma.sync.aligned.m16n8k16.row.col.f32.bf16.bf16.f32 "
        "{%0,%1,%2,%3}, {%4,%5,%6,%7}, {%8,%9}, {%0,%1,%2,%3};"
        : "+f"(c[0]), "+f"(c[1]), "+f"(c[2]), "+f"(c[3])
        : "r"(a[0]), "r"(a[1]), "r"(a[2]), "r"(a[3]), "r"(b[0]), "r"(b[1]));
}
__device__ __forceinline__ uint32_t pack2(float x, float y) {
    const __nv_bfloat162 h2 = __floats2bfloat162_rn(x, y);
    return *(const uint32_t*)&h2;
}

// ---------------------------------------------------------------------------
__global__ void reset_kernel() { g_count = 0; }

// ---------------------------------------------------------------------------
// Prep: bf16 hi/lo split of x (4 floats per thread).
// ---------------------------------------------------------------------------
__global__ void prep_x_kernel(const float* __restrict__ x)
{
    const size_t i = ((size_t)blockIdx.x * 256 + threadIdx.x) * 4;
    const float4 v = *(const float4*)(x + i);
    float hx = __bfloat162float(__float2bfloat16_rn(v.x));
    float hy = __bfloat162float(__float2bfloat16_rn(v.y));
    float hz = __bfloat162float(__float2bfloat16_rn(v.z));
    float hw = __bfloat162float(__float2bfloat16_rn(v.w));
    uint2 ho, lo;
    ho.x = pack2(hx, hy);
    ho.y = pack2(hz, hw);
    lo.x = pack2(v.x - hx, v.y - hy);
    lo.y = pack2(v.z - hz, v.w - hw);
    *(uint2*)((char*)g_xh16 + i * 2) = ho;
    *(uint2*)((char*)g_xl16 + i * 2) = lo;
}

// ---------------------------------------------------------------------------
// Prep: base_w -> bf16 hi/lo chunks [kc][n][k32].
// Thread handles (kc, n, 4 consecutive k).
// ---------------------------------------------------------------------------
__global__ void prep_b_kernel(const float* __restrict__ w)
{
    const int idx = blockIdx.x * 256 + threadIdx.x;    // 0..294911
    const int kc  = idx >> 11;            // /2048
    const int rem = idx & 2047;
    const int n   = rem >> 3;             // 0..255
    const int q   = rem & 7;              // k group of 4
    const int k0  = q * 4;

    float v[4], h[4];
#pragma unroll
    for (int j = 0; j < 4; j++) {
        v[j] = w[(size_t)(kc * 32 + k0 + j) * 256 + n];
        h[j] = __bfloat162float(__float2bfloat16_rn(v[j]));
    }
    uint2 ho, lo;
    ho.x = pack2(h[0], h[1]);
    ho.y = pack2(h[2], h[3]);
    lo.x = pack2(v[0] - h[0], v[1] - h[1]);
    lo.y = pack2(v[2] - h[2], v[3] - h[3]);
    const size_t off = ((size_t)kc * 256 + n) * 32 + k0;
    *(uint2*)((char*)g_Bh16 + off * 2) = ho;
    *(uint2*)((char*)g_Bl16 + off * 2) = lo;
}

// ---------------------------------------------------------------------------
// Stage 1: 3x3 conv + bias + ReLU via mma.sync m16n8k16 BF16x3 implicit GEMM.
// CTA: M=128 pixels, N=128 channels, K=4608 in 144 chunks of 32.
// 8 warps, warp tile 32x64. 3-stage cp.async pipeline (wait_group 1).
// ---------------------------------------------------------------------------
__global__ void __launch_bounds__(256, 1)
conv_mma_kernel(const float* __restrict__ bbase)
{
    extern __shared__ char smem[];
    const uint32_t sb = smem_u32(smem);
    const int tid  = threadIdx.x;
    const int wid  = tid >> 5;
    const int lane = tid & 31;
    const int g    = lane >> 2;
    const int t    = lane & 3;
    const int nblk = blockIdx.x;         // 0..1
    const int mblk = blockIdx.y;         // 0..1023
    const int wm   = (wid >> 1) * 32;    // warp row 0/32/64/96
    const int wn   = (wid & 1) * 64;     // warp col 0/64

    // fill-side mapping: thread -> (row 0..127, half 0/1), 64B each for A and B
    const int frow  = tid >> 1;
    const int fhalf = tid & 1;
    const int p  = mblk * 128 + frow;
    const int pb = p >> 12;
    const int ph = (p >> 6) & 63;
    const int pw = p & 63;

    float bias[16];
#pragma unroll
    for (int ni = 0; ni < 8; ni++) {
        const int ch = nblk * 128 + wn + ni * 8 + 2 * t;
        bias[2 * ni + 0] = __ldg(&bbase[ch + 0]);
        bias[2 * ni + 1] = __ldg(&bbase[ch + 1]);
    }

    float C[2][8][4];
#pragma unroll
    for (int mi = 0; mi < 2; mi++)
#pragma unroll
        for (int ni = 0; ni < 8; ni++)
#pragma unroll
            for (int r = 0; r < 4; r++) C[mi][ni][r] = 0.0f;

    auto fill = [&](int kc, int stg) {
        const uint32_t base = sb + (uint32_t)stg * STAGE;
        // A: pixel row `frow`, half `fhalf`, 32 bf16 = 64B
        const int pos = kc >> 4;                 // 16 chunks of 32 per position
        const int ky  = pos / 3;
        const int kx  = pos - ky * 3;
        const int hin = ph + ky - 1;
        const int win = pw + kx - 1;
        const bool valid = ((unsigned)hin < 64u) && ((unsigned)win < 64u);
        const int c0 = (kc & 15) * 32;
        const __nv_bfloat16* xsrc = fhalf ? g_xl16 : g_xh16;
        const char* asrc = valid
            ? (const char*)(xsrc + ((size_t)((pb * 64 + hin) * 64 + win)) * 512 + c0)
            : (const char*)g_zero;
        const uint32_t adst = base + (uint32_t)fhalf * A_HL +
                              (uint32_t)frow * AROW_B;
#pragma unroll
        for (int i = 0; i < 4; i++) cp16(adst + i * 16, asrc + i * 16);

        // B: n row `frow` within this CTA's 128-channel block, half `fhalf`
        const __nv_bfloat16* bsrc16 = fhalf ? g_Bl16 : g_Bh16;
        const char* bsrc = (const char*)(bsrc16 +
                           ((size_t)kc * 256 + nblk * 128 + frow) * 32);
        const uint32_t bdst = base + ABYTES + (uint32_t)fhalf * B_HL +
                              (uint32_t)frow * AROW_B;
#pragma unroll
        for (int i = 0; i < 4; i++) cp16(bdst + i * 16, bsrc + i * 16);

        asm volatile("cp.async.commit_group;" ::: "memory");
    };

    fill(0, 0);
    fill(1, 1);

#pragma unroll 1
    for (int step = 0; step < NSTEPS; step++) {
        if (step < NSTEPS - 1)
            asm volatile("cp.async.wait_group 1;" ::: "memory");
        else
            asm volatile("cp.async.wait_group 0;" ::: "memory");
        __syncthreads();
        if (step + 2 < NSTEPS) fill(step + 2, (step + 2) % NSTAGE);

        const uint32_t base = sb + (uint32_t)(step % NSTAGE) * STAGE;

#pragma unroll
        for (int s = 0; s < 2; s++) {            // two k16 groups per chunk
            const uint32_t ks = (uint32_t)s * 32;
            uint32_t ah[2][4], al[2][4];
#pragma unroll
            for (int mi = 0; mi < 2; mi++) {
                const uint32_t ad = base + (uint32_t)(wm + mi * 16 + g) * AROW_B
                                         + ks + (uint32_t)t * 4;
                ah[mi][0] = lds32b(ad);
                ah[mi][1] = lds32b(ad + 8 * AROW_B);
                ah[mi][2] = lds32b(ad + 16);
                ah[mi][3] = lds32b(ad + 8 * AROW_B + 16);
                al[mi][0] = lds32b(ad + A_HL);
                al[mi][1] = lds32b(ad + A_HL + 8 * AROW_B);
                al[mi][2] = lds32b(ad + A_HL + 16);
                al[mi][3] = lds32b(ad + A_HL + 8 * AROW_B + 16);
            }
            uint32_t bh[8][2], bl[8][2];
#pragma unroll
            for (int ni = 0; ni < 8; ni++) {
                const uint32_t bd = base + ABYTES +
                                    (uint32_t)(wn + ni * 8 + g) * AROW_B +
                                    ks + (uint32_t)t * 4;
                bh[ni][0] = lds32b(bd);
                bh[ni][1] = lds32b(bd + 16);
                bl[ni][0] = lds32b(bd + B_HL);
                bl[ni][1] = lds32b(bd + B_HL + 16);
            }
#pragma unroll
            for (int mi = 0; mi < 2; mi++)
#pragma unroll
                for (int ni = 0; ni < 8; ni++)
                    mma_bf16(C[mi][ni], ah[mi], bh[ni]);
#pragma unroll
            for (int mi = 0; mi < 2; mi++)
#pragma unroll
                for (int ni = 0; ni < 8; ni++)
                    mma_bf16(C[mi][ni], ah[mi], bl[ni]);
#pragma unroll
            for (int mi = 0; mi < 2; mi++)
#pragma unroll
                for (int ni = 0; ni < 8; ni++)
                    mma_bf16(C[mi][ni], al[mi], bh[ni]);
        }
    }

    // Epilogue: bias + ReLU -> g_feat
#pragma unroll
    for (int mi = 0; mi < 2; mi++) {
        const int row0 = mblk * 128 + wm + mi * 16 + g;
#pragma unroll
        for (int ni = 0; ni < 8; ni++) {
            const int ch = nblk * 128 + wn + ni * 8 + 2 * t;
            float2 v0, v1;
            v0.x = fmaxf(C[mi][ni][0] + bias[2 * ni + 0], 0.f);
            v0.y = fmaxf(C[mi][ni][1] + bias[2 * ni + 1], 0.f);
            v1.x = fmaxf(C[mi][ni][2] + bias[2 * ni + 0], 0.f);
            v1.y = fmaxf(C[mi][ni][3] + bias[2 * ni + 1], 0.f);
            *(float2*)(g_feat + (size_t)row0 * 256 + ch)       = v0;
            *(float2*)(g_feat + (size_t)(row0 + 8) * 256 + ch) = v1;
        }
    }
}

// ---------------------------------------------------------------------------
// Stage 2: fused 1x1 heads + sigmoid + anchor filter + concat store.
// Flags pixels with any anchor within delta of a decision threshold.
// ---------------------------------------------------------------------------
__global__ void __launch_bounds__(256)
rpn_head_kernel(const float* __restrict__ cls_w,
                const float* __restrict__ cls_b,
                const float* __restrict__ reg_w,
                const float* __restrict__ reg_b,
                float* __restrict__ out)
{
    __shared__ float wsm[256 * 45];
    for (int idx = threadIdx.x; idx < 256 * 45; idx += 256) {
        const int c = idx / 45;
        const int j = idx - c * 45;
        wsm[idx] = (j < 36) ? reg_w[c * 36 + j] : cls_w[c * 9 + (j - 36)];
    }
    __syncthreads();

    const int p = blockIdx.x * 256 + threadIdx.x;
    const float* f = g_feat + (size_t)p * 256;

    float acc[45];
#pragma unroll
    for (int j = 0; j < 45; j++) acc[j] = 0.0f;

#pragma unroll 1
    for (int c4 = 0; c4 < 64; c4++) {
        const float4 fv = *(const float4*)(f + c4 * 4);
        const float* w0 = &wsm[(c4 * 4 + 0) * 45];
        const float* w1 = &wsm[(c4 * 4 + 1) * 45];
        const float* w2 = &wsm[(c4 * 4 + 2) * 45];
        const float* w3 = &wsm[(c4 * 4 + 3) * 45];
#pragma unroll
        for (int j = 0; j < 45; j++) {
            float tt = acc[j];
            tt = fmaf(fv.x, w0[j], tt);
            tt = fmaf(fv.y, w1[j], tt);
            tt = fmaf(fv.z, w2[j], tt);
            tt = fmaf(fv.w, w3[j], tt);
            acc[j] = tt;
        }
    }

#pragma unroll
    for (int j = 0; j < 36; j++) acc[j] += reg_b[j];
#pragma unroll
    for (int a = 0; a < 9; a++) {
        const float z = acc[36 + a] + cls_b[a];
        acc[36 + a] = 1.0f / (1.0f + expf(-z));
    }

    bool flag = false;
    float* o = out + (size_t)p * 45;
#pragma unroll
    for (int a = 0; a < 9; a++) {
        const float obj = acc[36 + a];
        const float w2v = acc[4 * a + 2];
        const float h2v = acc[4 * a + 3];
        flag |= (fabsf(w2v - 10.0f) < DELTA_REG) ||
                (fabsf(h2v - 10.0f) < DELTA_REG) ||
                (fabsf(obj - 0.7f)  < DELTA_OBJ);
        const bool keep = (obj > 0.7f) && (w2v > 10.0f) && (h2v > 10.0f);
        const float m = keep ? 1.0f : 0.0f;
        o[4 * a + 0] = acc[4 * a + 0] * m;
        o[4 * a + 1] = acc[4 * a + 1] * m;
        o[4 * a + 2] = w2v * m;
        o[4 * a + 3] = h2v * m;
        o[36 + a]    = obj;
    }
    if (flag) {
        const int i = atomicAdd(&g_count, 1);
        g_list[i] = p;
    }
}

// ---------------------------------------------------------------------------
// Stage 3: exact fp32 repair of flagged (threshold-adjacent) pixels.
// ---------------------------------------------------------------------------
__global__ void __launch_bounds__(256)
repair_kernel(const float* __restrict__ x,  const float* __restrict__ w,
              const float* __restrict__ bbase,
              const float* __restrict__ cls_w, const float* __restrict__ cls_b,
              const float* __restrict__ reg_w, const float* __restrict__ reg_b,
              float* __restrict__ out)
{
    __shared__ float xs[KTOT];
    __shared__ float feats[256];
    __shared__ float hsm[45];
    const int tid = threadIdx.x;
    const int cnt = g_count;

    for (int it = blockIdx.x; it < cnt; it += gridDim.x) {
        const int p  = g_list[it];
        const int pb = p >> 12;
        const int ph = (p >> 6) & 63;
        const int pw = p & 63;

#pragma unroll 1
        for (int pos = 0; pos < 9; pos++) {
            const int ky = pos / 3;
            const int kx = pos - ky * 3;
            const int hin = ph + ky - 1;
            const int win = pw + kx - 1;
            const bool valid = ((unsigned)hin < 64u) && ((unsigned)win < 64u);
            const float* src = x + ((size_t)((pb * 64 + hin) * 64 + win)) * 512;
#pragma unroll
            for (int c = tid; c < 512; c += 256)
                xs[pos * 512 + c] = valid ? src[c] : 0.0f;
        }
        __syncthreads();

        float a0 = 0.f, a1 = 0.f, a2 = 0.f, a3 = 0.f;
#pragma unroll 4
        for (int kk = 0; kk < KTOT; kk += 4) {
            a0 = fmaf(xs[kk + 0], w[(size_t)(kk + 0) * 256 + tid], a0);
            a1 = fmaf(xs[kk + 1], w[(size_t)(kk + 1) * 256 + tid], a1);
            a2 = fmaf(xs[kk + 2], w[(size_t)(kk + 2) * 256 + tid], a2);
            a3 = fmaf(xs[kk + 3], w[(size_t)(kk + 3) * 256 + tid], a3);
        }
        feats[tid] = fmaxf((a0 + a1) + (a2 + a3) + bbase[tid], 0.0f);
        __syncthreads();

        if (tid < 45) {
            float a = 0.f;
            if (tid < 36) {
#pragma unroll 4
                for (int c = 0; c < 256; c++)
                    a = fmaf(feats[c], reg_w[c * 36 + tid], a);
                a += reg_b[tid];
            } else {
                const int j = tid - 36;
#pragma unroll 4
                for (int c = 0; c < 256; c++)
                    a = fmaf(feats[c], cls_w[c * 9 + j], a);
                a = 1.0f / (1.0f + expf(-(a + cls_b[j])));
            }
            hsm[tid] = a;
        }
        __syncthreads();

        if (tid < 9) {
            const int a4 = tid * 4;
            const float obj = hsm[36 + tid];
            const bool keep = (obj > 0.7f) && (hsm[a4 + 2] > 10.0f) &&
                              (hsm[a4 + 3] > 10.0f);
            const float m = keep ? 1.0f : 0.0f;
            float* o = out + (size_t)p * 45;
            o[a4 + 0] = hsm[a4 + 0] * m;
            o[a4 + 1] = hsm[a4 + 1] * m;
            o[a4 + 2] = hsm[a4 + 2] * m;
            o[a4 + 3] = hsm[a4 + 3] * m;
            o[36 + tid] = obj;
        }
        __syncthreads();
    }
}

extern "C" void kernel_launch(void* const* d_in, const int* in_sizes, int n_in,
                              void* d_out, int out_size)
{
    const float* x      = (const float*)d_in[0];
    const float* base_w = (const float*)d_in[1];
    const float* base_b = (const float*)d_in[2];
    const float* cls_w  = (const float*)d_in[3];
    const float* cls_b  = (const float*)d_in[4];
    const float* reg_w  = (const float*)d_in[5];
    const float* reg_b  = (const float*)d_in[6];
    float* out = (float*)d_out;

    cudaFuncSetAttribute(conv_mma_kernel,
                         cudaFuncAttributeMaxDynamicSharedMemorySize, SMEM_TOTAL);

    reset_kernel<<<1, 1>>>();
    prep_x_kernel<<<(NPIX * 512 / 4) / 256, 256>>>(x);
    prep_b_kernel<<<(KCH * 256 * 8) / 256, 256>>>(base_w);

    dim3 g1(2, 1024, 1);
    conv_mma_kernel<<<g1, 256, SMEM_TOTAL>>>(base_b);
    rpn_head_kernel<<<512, 256>>>(cls_w, cls_b, reg_w, reg_b, out);
    repair_kernel<<<256, 256>>>(x, base_w, base_b, cls_w, cls_b,
                                reg_w, reg_b, out);
}

// round 15
// speedup vs baseline: 2.0383x; 1.2425x over previous
#include <cuda_runtime.h>
#include <cuda_bf16.h>
#include <math.h>
#include <stdint.h>

// Shapes:
//   x      [32,64,64,512] f32 NHWC
//   base_w [3,3,512,256]  HWIO   (flattened: w[kk*256+n], kk = pos*512+c)
//   base_b [256]
//   cls_w  [1,1,256,9], cls_b [9]
//   reg_w  [1,1,256,36], reg_b [36]
//   out    [32,64,64,45]

#define NPIX    (32 * 64 * 64)
#define KTOT    4608
#define KCH     144                 // k chunks of 32
#define NSTEPS  144
#define AROW_B  80                  // 32 bf16 = 64B + 16B pad (ldmatrix conflict-free)
#define A_HL    (128 * AROW_B)      // 10240 B per A half
#define B_HL    (256 * AROW_B)      // 20480 B per B half (256 n-rows)
#define ABYTES  (2 * A_HL)          // 20480
#define BBYTES  (2 * B_HL)          // 40960
#define STAGE   (ABYTES + BBYTES)   // 61440
#define SMEM_TOTAL (2 * STAGE)      // 122880

#define DELTA_REG 5e-3f
#define DELTA_OBJ 5e-4f

__device__ float g_feat[(size_t)NPIX * 256];
__device__ __align__(256) __nv_bfloat16 g_xh16[(size_t)NPIX * 512];
__device__ __align__(256) __nv_bfloat16 g_xl16[(size_t)NPIX * 512];
// B chunks: [kc][n 256][k 32] bf16 -> conv-side fill is a linear copy.
__device__ __align__(256) __nv_bfloat16 g_Bh16[(size_t)KCH * 256 * 32];
__device__ __align__(256) __nv_bfloat16 g_Bl16[(size_t)KCH * 256 * 32];
__device__ __align__(256) float g_zero[16];   // 64B, stays zero
__device__ int g_count;
__device__ int g_list[NPIX];

// ---------------- helpers ----------------
__device__ __forceinline__ uint32_t smem_u32(const void* p) {
    uint32_t a;
    asm("{ .reg .u64 t; cvta.to.shared.u64 t, %1; cvt.u32.u64 %0, t; }"
        : "=r"(a) : "l"(p));
    return a;
}
__device__ __forceinline__ void cp16(uint32_t d, const void* s) {
    asm volatile("cp.async.ca.shared.global [%0], [%1], 16;"
                 :: "r"(d), "l"(s) : "memory");
}
__device__ __forceinline__ void ldm_x4(uint32_t* r, uint32_t addr) {
    asm volatile("ldmatrix.sync.aligned.m8n8.x4.shared.b16 {%0,%1,%2,%3}, [%4];"
                 : "=r"(r[0]), "=r"(r[1]), "=r"(r[2]), "=r"(r[3]) : "r"(addr));
}
__device__ __forceinline__ void mma_bf16(float* c, const uint32_t* a,
                                         uint32_t b0, uint32_t b1) {
    asm volatile(
        "mma.sync.aligned.m16n8k16.row.col.f32.bf16.bf16.f32 "
        "{%0,%1,%2,%3}, {%4,%5,%6,%7}, {%8,%9}, {%0,%1,%2,%3};"
        : "+f"(c[0]), "+f"(c[1]), "+f"(c[2]), "+f"(c[3])
        : "r"(a[0]), "r"(a[1]), "r"(a[2]), "r"(a[3]), "r"(b0), "r"(b1));
}
__device__ __forceinline__ uint32_t pack2(float x, float y) {
    const __nv_bfloat162 h2 = __floats2bfloat162_rn(x, y);
    return *(const uint32_t*)&h2;
}

// ---------------------------------------------------------------------------
__global__ void reset_kernel() { g_count = 0; }

// ---------------------------------------------------------------------------
// Prep: bf16 hi/lo split of x (4 floats per thread).
// ---------------------------------------------------------------------------
__global__ void prep_x_kernel(const float* __restrict__ x)
{
    const size_t i = ((size_t)blockIdx.x * 256 + threadIdx.x) * 4;
    const float4 v = *(const float4*)(x + i);
    float hx = __bfloat162float(__float2bfloat16_rn(v.x));
    float hy = __bfloat162float(__float2bfloat16_rn(v.y));
    float hz = __bfloat162float(__float2bfloat16_rn(v.z));
    float hw = __bfloat162float(__float2bfloat16_rn(v.w));
    uint2 ho, lo;
    ho.x = pack2(hx, hy);
    ho.y = pack2(hz, hw);
    lo.x = pack2(v.x - hx, v.y - hy);
    lo.y = pack2(v.z - hz, v.w - hw);
    *(uint2*)((char*)g_xh16 + i * 2) = ho;
    *(uint2*)((char*)g_xl16 + i * 2) = lo;
}

// ---------------------------------------------------------------------------
// Prep: base_w -> bf16 hi/lo chunks [kc][n][k32].
// ---------------------------------------------------------------------------
__global__ void prep_b_kernel(const float* __restrict__ w)
{
    const int idx = blockIdx.x * 256 + threadIdx.x;    // 0..294911
    const int kc  = idx >> 11;
    const int rem = idx & 2047;
    const int n   = rem >> 3;
    const int q   = rem & 7;
    const int k0  = q * 4;

    float v[4], h[4];
#pragma unroll
    for (int j = 0; j < 4; j++) {
        v[j] = w[(size_t)(kc * 32 + k0 + j) * 256 + n];
        h[j] = __bfloat162float(__float2bfloat16_rn(v[j]));
    }
    uint2 ho, lo;
    ho.x = pack2(h[0], h[1]);
    ho.y = pack2(h[2], h[3]);
    lo.x = pack2(v[0] - h[0], v[1] - h[1]);
    lo.y = pack2(v[2] - h[2], v[3] - h[3]);
    const size_t off = ((size_t)kc * 256 + n) * 32 + k0;
    *(uint2*)((char*)g_Bh16 + off * 2) = ho;
    *(uint2*)((char*)g_Bl16 + off * 2) = lo;
}

// ---------------------------------------------------------------------------
// Stage 1: 3x3 conv + bias + ReLU via mma.sync m16n8k16 BF16x3 implicit GEMM.
// CTA: 512 threads (16 warps, 4x4 warp grid), tile M=128 x N=256,
// K=4608 in 144 chunks of 32. ldmatrix fragment loads, 2-stage cp.async.
// ---------------------------------------------------------------------------
__global__ void __launch_bounds__(512, 1)
conv_mma_kernel(const float* __restrict__ bbase)
{
    extern __shared__ char smem[];
    const uint32_t sb = smem_u32(smem);
    const int tid  = threadIdx.x;
    const int wid  = tid >> 5;
    const int lane = tid & 31;
    const int g    = lane >> 2;
    const int t    = lane & 3;
    const int mblk = blockIdx.x;          // 0..1023
    const int wm   = (wid >> 2) * 32;     // warp row 0/32/64/96
    const int wn   = (wid & 3) * 64;      // warp col 0/64/128/192

    // ---- fill-side mappings ----
    // A: 512 slots = 128 rows x 2 halves x 2 parts(32B)
    const int arow  = tid >> 2;
    const int ahalf = (tid >> 1) & 1;
    const int apart = tid & 1;
    const int p  = mblk * 128 + arow;
    const int pb = p >> 12;
    const int ph = (p >> 6) & 63;
    const int pw = p & 63;
    // B: 512 slots = 256 n-rows x 2 halves (64B each)
    const int bn    = tid >> 1;
    const int bhalf = tid & 1;

    // ldmatrix lane offset: rows via lane%16, k(+8) via lane/16
    const uint32_t lmoff = (uint32_t)(lane & 15) * AROW_B +
                           (uint32_t)(lane >> 4) * 16;

    float bias[16];
#pragma unroll
    for (int ni = 0; ni < 8; ni++) {
        const int ch = wn + ni * 8 + 2 * t;
        bias[2 * ni + 0] = __ldg(&bbase[ch + 0]);
        bias[2 * ni + 1] = __ldg(&bbase[ch + 1]);
    }

    float C[2][8][4];
#pragma unroll
    for (int mi = 0; mi < 2; mi++)
#pragma unroll
        for (int ni = 0; ni < 8; ni++)
#pragma unroll
            for (int r = 0; r < 4; r++) C[mi][ni][r] = 0.0f;

    auto fill = [&](int kc, int stg) {
        const uint32_t base = sb + (uint32_t)stg * STAGE;
        // A slice
        const int pos = kc >> 4;
        const int ky  = pos / 3;
        const int kx  = pos - ky * 3;
        const int hin = ph + ky - 1;
        const int win = pw + kx - 1;
        const bool valid = ((unsigned)hin < 64u) && ((unsigned)win < 64u);
        const int c0 = (kc & 15) * 32 + apart * 16;
        const __nv_bfloat16* xsrc = ahalf ? g_xl16 : g_xh16;
        const char* asrc = valid
            ? (const char*)(xsrc + ((size_t)((pb * 64 + hin) * 64 + win)) * 512 + c0)
            : (const char*)g_zero;
        const uint32_t adst = base + (uint32_t)ahalf * A_HL +
                              (uint32_t)arow * AROW_B + (uint32_t)apart * 32;
        cp16(adst,      asrc);
        cp16(adst + 16, asrc + 16);

        // B slice (linear copy of pre-chunked weights)
        const __nv_bfloat16* bsrc16 = bhalf ? g_Bl16 : g_Bh16;
        const char* bsrc = (const char*)(bsrc16 + ((size_t)kc * 256 + bn) * 32);
        const uint32_t bdst = base + ABYTES + (uint32_t)bhalf * B_HL +
                              (uint32_t)bn * AROW_B;
#pragma unroll
        for (int i = 0; i < 4; i++) cp16(bdst + i * 16, bsrc + i * 16);

        asm volatile("cp.async.commit_group;" ::: "memory");
    };

    fill(0, 0);

#pragma unroll 1
    for (int step = 0; step < NSTEPS; step++) {
        asm volatile("cp.async.wait_group 0;" ::: "memory");
        __syncthreads();
        if (step + 1 < NSTEPS) fill(step + 1, (step + 1) & 1);

        const uint32_t base  = sb + (uint32_t)(step & 1) * STAGE;
        const uint32_t abase = base + (uint32_t)wm * AROW_B + lmoff;
        const uint32_t bbs   = base + ABYTES + (uint32_t)wn * AROW_B + lmoff;

#pragma unroll
        for (int s = 0; s < 2; s++) {            // two k16 groups per chunk
            const uint32_t ks = (uint32_t)s * 32;

            uint32_t ah[2][4];
            ldm_x4(ah[0], abase + ks);
            ldm_x4(ah[1], abase + 16 * AROW_B + ks);

            uint32_t bh[4][4];                   // [nq]: r0=b0(ni even) r1=b0(odd)
#pragma unroll                                   //       r2=b1(even)  r3=b1(odd)
            for (int nq = 0; nq < 4; nq++)
                ldm_x4(bh[nq], bbs + (uint32_t)nq * 16 * AROW_B + ks);

            // pass hh
#pragma unroll
            for (int mi = 0; mi < 2; mi++)
#pragma unroll
                for (int nq = 0; nq < 4; nq++) {
                    mma_bf16(C[mi][2 * nq + 0], ah[mi], bh[nq][0], bh[nq][2]);
                    mma_bf16(C[mi][2 * nq + 1], ah[mi], bh[nq][1], bh[nq][3]);
                }

            // pass lh (al x bh)
            uint32_t al[2][4];
            ldm_x4(al[0], abase + A_HL + ks);
            ldm_x4(al[1], abase + A_HL + 16 * AROW_B + ks);
#pragma unroll
            for (int mi = 0; mi < 2; mi++)
#pragma unroll
                for (int nq = 0; nq < 4; nq++) {
                    mma_bf16(C[mi][2 * nq + 0], al[mi], bh[nq][0], bh[nq][2]);
                    mma_bf16(C[mi][2 * nq + 1], al[mi], bh[nq][1], bh[nq][3]);
                }

            // pass hl (ah x bl)
            uint32_t bl[4][4];
#pragma unroll
            for (int nq = 0; nq < 4; nq++)
                ldm_x4(bl[nq], bbs + B_HL + (uint32_t)nq * 16 * AROW_B + ks);
#pragma unroll
            for (int mi = 0; mi < 2; mi++)
#pragma unroll
                for (int nq = 0; nq < 4; nq++) {
                    mma_bf16(C[mi][2 * nq + 0], ah[mi], bl[nq][0], bl[nq][2]);
                    mma_bf16(C[mi][2 * nq + 1], ah[mi], bl[nq][1], bl[nq][3]);
                }
        }
    }

    // Epilogue: bias + ReLU -> g_feat
#pragma unroll
    for (int mi = 0; mi < 2; mi++) {
        const int row0 = mblk * 128 + wm + mi * 16 + g;
#pragma unroll
        for (int ni = 0; ni < 8; ni++) {
            const int ch = wn + ni * 8 + 2 * t;
            float2 v0, v1;
            v0.x = fmaxf(C[mi][ni][0] + bias[2 * ni + 0], 0.f);
            v0.y = fmaxf(C[mi][ni][1] + bias[2 * ni + 1], 0.f);
            v1.x = fmaxf(C[mi][ni][2] + bias[2 * ni + 0], 0.f);
            v1.y = fmaxf(C[mi][ni][3] + bias[2 * ni + 1], 0.f);
            *(float2*)(g_feat + (size_t)row0 * 256 + ch)       = v0;
            *(float2*)(g_feat + (size_t)(row0 + 8) * 256 + ch) = v1;
        }
    }
}

// ---------------------------------------------------------------------------
// Stage 2: fused 1x1 heads + sigmoid + anchor filter + concat store.
// Flags pixels with any anchor within delta of a decision threshold.
// ---------------------------------------------------------------------------
__global__ void __launch_bounds__(256)
rpn_head_kernel(const float* __restrict__ cls_w,
                const float* __restrict__ cls_b,
                const float* __restrict__ reg_w,
                const float* __restrict__ reg_b,
                float* __restrict__ out)
{
    __shared__ float wsm[256 * 45];
    for (int idx = threadIdx.x; idx < 256 * 45; idx += 256) {
        const int c = idx / 45;
        const int j = idx - c * 45;
        wsm[idx] = (j < 36) ? reg_w[c * 36 + j] : cls_w[c * 9 + (j - 36)];
    }
    __syncthreads();

    const int p = blockIdx.x * 256 + threadIdx.x;
    const float* f = g_feat + (size_t)p * 256;

    float acc[45];
#pragma unroll
    for (int j = 0; j < 45; j++) acc[j] = 0.0f;

#pragma unroll 1
    for (int c4 = 0; c4 < 64; c4++) {
        const float4 fv = *(const float4*)(f + c4 * 4);
        const float* w0 = &wsm[(c4 * 4 + 0) * 45];
        const float* w1 = &wsm[(c4 * 4 + 1) * 45];
        const float* w2 = &wsm[(c4 * 4 + 2) * 45];
        const float* w3 = &wsm[(c4 * 4 + 3) * 45];
#pragma unroll
        for (int j = 0; j < 45; j++) {
            float tt = acc[j];
            tt = fmaf(fv.x, w0[j], tt);
            tt = fmaf(fv.y, w1[j], tt);
            tt = fmaf(fv.z, w2[j], tt);
            tt = fmaf(fv.w, w3[j], tt);
            acc[j] = tt;
        }
    }

#pragma unroll
    for (int j = 0; j < 36; j++) acc[j] += reg_b[j];
#pragma unroll
    for (int a = 0; a < 9; a++) {
        const float z = acc[36 + a] + cls_b[a];
        acc[36 + a] = 1.0f / (1.0f + expf(-z));
    }

    bool flag = false;
    float* o = out + (size_t)p * 45;
#pragma unroll
    for (int a = 0; a < 9; a++) {
        const float obj = acc[36 + a];
        const float w2v = acc[4 * a + 2];
        const float h2v = acc[4 * a + 3];
        flag |= (fabsf(w2v - 10.0f) < DELTA_REG) ||
                (fabsf(h2v - 10.0f) < DELTA_REG) ||
                (fabsf(obj - 0.7f)  < DELTA_OBJ);
        const bool keep = (obj > 0.7f) && (w2v > 10.0f) && (h2v > 10.0f);
        const float m = keep ? 1.0f : 0.0f;
        o[4 * a + 0] = acc[4 * a + 0] * m;
        o[4 * a + 1] = acc[4 * a + 1] * m;
        o[4 * a + 2] = w2v * m;
        o[4 * a + 3] = h2v * m;
        o[36 + a]    = obj;
    }
    if (flag) {
        const int i = atomicAdd(&g_count, 1);
        g_list[i] = p;
    }
}

// ---------------------------------------------------------------------------
// Stage 3: exact fp32 repair of flagged (threshold-adjacent) pixels.
// ---------------------------------------------------------------------------
__global__ void __launch_bounds__(256)
repair_kernel(const float* __restrict__ x,  const float* __restrict__ w,
              const float* __restrict__ bbase,
              const float* __restrict__ cls_w, const float* __restrict__ cls_b,
              const float* __restrict__ reg_w, const float* __restrict__ reg_b,
              float* __restrict__ out)
{
    __shared__ float xs[KTOT];
    __shared__ float feats[256];
    __shared__ float hsm[45];
    const int tid = threadIdx.x;
    const int cnt = g_count;

    for (int it = blockIdx.x; it < cnt; it += gridDim.x) {
        const int p  = g_list[it];
        const int pb = p >> 12;
        const int ph = (p >> 6) & 63;
        const int pw = p & 63;

#pragma unroll 1
        for (int pos = 0; pos < 9; pos++) {
            const int ky = pos / 3;
            const int kx = pos - ky * 3;
            const int hin = ph + ky - 1;
            const int win = pw + kx - 1;
            const bool valid = ((unsigned)hin < 64u) && ((unsigned)win < 64u);
            const float* src = x + ((size_t)((pb * 64 + hin) * 64 + win)) * 512;
#pragma unroll
            for (int c = tid; c < 512; c += 256)
                xs[pos * 512 + c] = valid ? src[c] : 0.0f;
        }
        __syncthreads();

        float a0 = 0.f, a1 = 0.f, a2 = 0.f, a3 = 0.f;
#pragma unroll 4
        for (int kk = 0; kk < KTOT; kk += 4) {
            a0 = fmaf(xs[kk + 0], w[(size_t)(kk + 0) * 256 + tid], a0);
            a1 = fmaf(xs[kk + 1], w[(size_t)(kk + 1) * 256 + tid], a1);
            a2 = fmaf(xs[kk + 2], w[(size_t)(kk + 2) * 256 + tid], a2);
            a3 = fmaf(xs[kk + 3], w[(size_t)(kk + 3) * 256 + tid], a3);
        }
        feats[tid] = fmaxf((a0 + a1) + (a2 + a3) + bbase[tid], 0.0f);
        __syncthreads();

        if (tid < 45) {
            float a = 0.f;
            if (tid < 36) {
#pragma unroll 4
                for (int c = 0; c < 256; c++)
                    a = fmaf(feats[c], reg_w[c * 36 + tid], a);
                a += reg_b[tid];
            } else {
                const int j = tid - 36;
#pragma unroll 4
                for (int c = 0; c < 256; c++)
                    a = fmaf(feats[c], cls_w[c * 9 + j], a);
                a = 1.0f / (1.0f + expf(-(a + cls_b[j])));
            }
            hsm[tid] = a;
        }
        __syncthreads();

        if (tid < 9) {
            const int a4 = tid * 4;
            const float obj = hsm[36 + tid];
            const bool keep = (obj > 0.7f) && (hsm[a4 + 2] > 10.0f) &&
                              (hsm[a4 + 3] > 10.0f);
            const float m = keep ? 1.0f : 0.0f;
            float* o = out + (size_t)p * 45;
            o[a4 + 0] = hsm[a4 + 0] * m;
            o[a4 + 1] = hsm[a4 + 1] * m;
            o[a4 + 2] = hsm[a4 + 2] * m;
            o[a4 + 3] = hsm[a4 + 3] * m;
            o[36 + tid] = obj;
        }
        __syncthreads();
    }
}

extern "C" void kernel_launch(void* const* d_in, const int* in_sizes, int n_in,
                              void* d_out, int out_size)
{
    const float* x      = (const float*)d_in[0];
    const float* base_w = (const float*)d_in[1];
    const float* base_b = (const float*)d_in[2];
    const float* cls_w  = (const float*)d_in[3];
    const float* cls_b  = (const float*)d_in[4];
    const float* reg_w  = (const float*)d_in[5];
    const float* reg_b  = (const float*)d_in[6];
    float* out = (float*)d_out;

    cudaFuncSetAttribute(conv_mma_kernel,
                         cudaFuncAttributeMaxDynamicSharedMemorySize, SMEM_TOTAL);

    reset_kernel<<<1, 1>>>();
    prep_x_kernel<<<(NPIX * 512 / 4) / 256, 256>>>(x);
    prep_b_kernel<<<(KCH * 256 * 8) / 256, 256>>>(base_w);

    conv_mma_kernel<<<1024, 512, SMEM_TOTAL>>>(base_b);
    rpn_head_kernel<<<512, 256>>>(cls_w, cls_b, reg_w, reg_b, out);
    repair_kernel<<<256, 256>>>(x, base_w, base_b, cls_w, cls_b,
                                reg_w, reg_b, out);
}